// round 6
// baseline (speedup 1.0000x reference)
#include <cuda_runtime.h>
#include <cuda_bf16.h>
#include <cstdint>
#include <math.h>

#define HEPS   1e-7f
#define HMAXN  (1.0f - 1e-5f)

// ---------------- precomputed bf16 split of W ----------------
__device__ __align__(16) __nv_bfloat16 g_Whi[256 * 256];
__device__ __align__(16) __nv_bfloat16 g_Wlo[256 * 256];

__global__ void wconv_kernel(const float* __restrict__ W) {
    int i = blockIdx.x * blockDim.x + threadIdx.x;
    if (i < 256 * 256) {
        float w = W[i];
        __nv_bfloat16 h = __float2bfloat16_rn(w);
        g_Whi[i] = h;
        g_Wlo[i] = __float2bfloat16_rn(w - __bfloat162float(h));
    }
}

// ---------------- PTX helpers (all family-wide, compute_103-safe) ----------
#define LDSM4(R, addr)                                                        \
    asm volatile("ldmatrix.sync.aligned.m8n8.x4.shared.b16 {%0,%1,%2,%3}, [%4];" \
        : "=r"((R)[0]), "=r"((R)[1]), "=r"((R)[2]), "=r"((R)[3]) : "r"(addr))

#define MMA_BF16(D, A, B0, B1)                                                \
    asm volatile("mma.sync.aligned.m16n8k16.row.col.f32.bf16.bf16.f32 "       \
        "{%0,%1,%2,%3},{%4,%5,%6,%7},{%8,%9},{%0,%1,%2,%3};"                  \
        : "+f"((D)[0]), "+f"((D)[1]), "+f"((D)[2]), "+f"((D)[3])              \
        : "r"((A)[0]), "r"((A)[1]), "r"((A)[2]), "r"((A)[3]), "r"(B0), "r"(B1))

#define CP_ASYNC16(saddr, gaddr)                                              \
    asm volatile("cp.async.cg.shared.global [%0], [%1], 16;" :: "r"(saddr), "l"(gaddr))
#define CP_COMMIT()  asm volatile("cp.async.commit_group;" ::: "memory")
#define CP_WAIT0()   asm volatile("cp.async.wait_group 0;" ::: "memory")

__device__ __forceinline__ uint32_t smem_u32(const void* p) {
    return (uint32_t)__cvta_generic_to_shared(p);
}
__device__ __forceinline__ uint32_t pack_bf2(float a, float b) {
    __nv_bfloat162 t = __floats2bfloat162_rn(a, b);
    return reinterpret_cast<uint32_t&>(t);
}

// per-row hyperbolic scalars: out_j = Ca*mx_j + Cb*b_j  (validated in R2)
__device__ __forceinline__ float2 hyp_scalars(float x2, float mx2, float adb, float b2sum) {
    float xn  = fmaxf(sqrtf(x2),  HEPS);
    float mxn = fmaxf(sqrtf(mx2), HEPS);
    float xc  = fminf(xn, 1.0f - 1e-7f);
    float at  = 0.5f * (log1pf(xc) - log1pf(-xc));
    float tt  = tanhf(mxn / xn * at);
    float s1  = tt / mxn;
    float rn  = fmaxf(sqrtf(s1 * s1 * mx2), HEPS);
    float ps  = (rn > HMAXN) ? (HMAXN / rn) : 1.0f;
    float sres = s1 * ps;
    float res2 = sres * sres * mx2;

    float omr = 1.0f - res2;
    float vn  = fmaxf(sqrtf(omr * omr * b2sum), HEPS);
    float lam = 2.0f / fmaxf(omr, HEPS);
    float sc2 = tanhf(0.5f * lam * vn);
    float ksec = sc2 * omr / vn;

    float xy  = ksec * sres * adb;
    float y2  = ksec * ksec * b2sum;
    float den = fmaxf(1.0f + 2.0f * xy + res2 * y2, HEPS);
    float ca  = (1.0f + 2.0f * xy + y2) * sres / den;
    float cb  = omr * ksec / den;

    float o2  = ca * ca * mx2 + 2.0f * ca * cb * adb + cb * cb * b2sum;
    float on  = fmaxf(sqrtf(o2), HEPS);
    float pf  = (on > HMAXN) ? (HMAXN / on) : 1.0f;
    return make_float2(pf * ca, pf * cb);
}

// smem layout per buffer (64B row stride, 16B-unit XOR swizzle):
//   A_hi 8K | A_lo 8K | B_hi 16K | B_lo 16K   = 48K, double buffered = 96K
#define BUFS  49152
#define AHI   0
#define ALO   8192
#define BHI   16384
#define BLO   32768
#define DSMEM_BYTES (1024 + 2 * BUFS)

__global__ __launch_bounds__(256, 1)
void hyplin_hmma_kernel(const float* __restrict__ x,
                        const float* __restrict__ b,
                        float* __restrict__ out,
                        int Nrows)
{
    extern __shared__ char dsm_raw[];
    __shared__ float bsm[256];
    __shared__ float bpart[8];

    const int tid  = threadIdx.x;
    const int w    = tid >> 5;
    const int l    = tid & 31;
    const int rowbase = blockIdx.x * 128;

    // align dynamic smem to 1024B
    uint32_t raw = smem_u32(dsm_raw);
    uint32_t sbase = (raw + 1023u) & ~1023u;
    char* dsm = dsm_raw + (sbase - raw);

    // ---- bias + ||b||^2 ----
    {
        float bv = b[tid];
        bsm[tid] = bv;
        float sq = bv * bv;
#pragma unroll
        for (int off = 16; off; off >>= 1)
            sq += __shfl_xor_sync(0xffffffffu, sq, off);
        if (l == 0) bpart[w] = sq;
    }
    __syncthreads();
    float b2sum = 0.f;
#pragma unroll
    for (int i = 0; i < 8; i++) b2sum += bpart[i];

    // ---- loader mappings ----
    // A: thread t loads 16 fp32 of row (t>>1), cols (t&1)*16 .. +16
    const int arow = tid >> 1;
    int rg = rowbase + arow; if (rg >= Nrows) rg = Nrows - 1;
    const float* xrow = x + (size_t)rg * 256 + (tid & 1) * 16;
    const int asw = (arow >> 1) & 3;
    const int ac2 = (tid & 1) * 2;
    const uint32_t astoff0 = arow * 64 + ((ac2 + 0) ^ asw) * 16;
    const uint32_t astoff1 = arow * 64 + ((ac2 + 1) ^ asw) * 16;

    // B cp.async: thread handles uint4 idx = tid + j*256 (j=0..3) per matrix
    const int bc = tid & 3;                 // 16B unit (pre-swizzle)
    const int brow0 = tid >> 2;             // + 64*j

    float x2p = 0.f;
    float acc[128];
#pragma unroll
    for (int i = 0; i < 128; i++) acc[i] = 0.f;

    // ---- prologue: chunk 0 ----
    {
        float4 a0 = reinterpret_cast<const float4*>(xrow)[0];
        float4 a1 = reinterpret_cast<const float4*>(xrow)[1];
        float4 a2 = reinterpret_cast<const float4*>(xrow)[2];
        float4 a3 = reinterpret_cast<const float4*>(xrow)[3];
#pragma unroll
        for (int j = 0; j < 4; j++) {
            int row = brow0 + j * 64;
            uint32_t unit = (uint32_t)(bc ^ ((row >> 1) & 3));
            uint32_t so = sbase + BHI + row * 64 + unit * 16;
            const char* gh = (const char*)(g_Whi + (size_t)row * 256 + bc * 8);
            const char* gl = (const char*)(g_Wlo + (size_t)row * 256 + bc * 8);
            CP_ASYNC16(so, gh);
            CP_ASYNC16(so + 16384, gl);
        }
        CP_COMMIT();
        float f[16] = {a0.x,a0.y,a0.z,a0.w, a1.x,a1.y,a1.z,a1.w,
                       a2.x,a2.y,a2.z,a2.w, a3.x,a3.y,a3.z,a3.w};
        uint32_t H[8], L[8];
#pragma unroll
        for (int e = 0; e < 16; e += 2) {
            x2p = fmaf(f[e], f[e], fmaf(f[e+1], f[e+1], x2p));
            float h0 = __bfloat162float(__float2bfloat16_rn(f[e]));
            float h1 = __bfloat162float(__float2bfloat16_rn(f[e+1]));
            H[e>>1] = pack_bf2(f[e], f[e+1]);
            L[e>>1] = pack_bf2(f[e] - h0, f[e+1] - h1);
        }
        *reinterpret_cast<uint4*>(dsm + AHI + astoff0) = make_uint4(H[0],H[1],H[2],H[3]);
        *reinterpret_cast<uint4*>(dsm + AHI + astoff1) = make_uint4(H[4],H[5],H[6],H[7]);
        *reinterpret_cast<uint4*>(dsm + ALO + astoff0) = make_uint4(L[0],L[1],L[2],L[3]);
        *reinterpret_cast<uint4*>(dsm + ALO + astoff1) = make_uint4(L[4],L[5],L[6],L[7]);
        CP_WAIT0();
    }
    __syncthreads();

    // ---- ldmatrix lane address bases (buffer 0, ks=0) ----
    const int rowA = 16 * w + (l & 15);
    const uint32_t addrA0 = sbase + AHI + rowA * 64 +
                            (((l >> 4) ^ ((rowA >> 1) & 3)) * 16);
    const int nB   = (l & 7) + ((l >> 4) << 3);
    const int klo  = (l >> 3) & 1;
    const uint32_t addrB0 = sbase + BHI + nB * 64 +
                            ((klo ^ ((nB >> 1) & 3)) * 16);

    // ---- main pipelined loop over 8 K-chunks ----
    for (int s = 0; s < 8; s++) {
        const uint32_t bufo  = (uint32_t)(s & 1) * BUFS;
        const uint32_t nbufo = (uint32_t)((s + 1) & 1) * BUFS;

        // prefetch next chunk: A into regs, B via cp.async
        float4 a0, a1, a2, a3;
        if (s < 7) {
            const float* src = xrow + (s + 1) * 32;
            a0 = reinterpret_cast<const float4*>(src)[0];
            a1 = reinterpret_cast<const float4*>(src)[1];
            a2 = reinterpret_cast<const float4*>(src)[2];
            a3 = reinterpret_cast<const float4*>(src)[3];
#pragma unroll
            for (int j = 0; j < 4; j++) {
                int row = brow0 + j * 64;
                uint32_t unit = (uint32_t)(bc ^ ((row >> 1) & 3));
                uint32_t so = sbase + nbufo + BHI + row * 64 + unit * 16;
                const char* gh = (const char*)(g_Whi + (size_t)row * 256 + (s+1) * 32 + bc * 8);
                const char* gl = (const char*)(g_Wlo + (size_t)row * 256 + (s+1) * 32 + bc * 8);
                CP_ASYNC16(so, gh);
                CP_ASYNC16(so + 16384, gl);
            }
            CP_COMMIT();
        }

        // ---- MMA over this chunk (KT=32 -> 2 ksteps of k16) ----
        uint32_t aHi[4], aLo[4], bh[4], bl[4];
#pragma unroll
        for (int ks = 0; ks < 2; ks++) {
            uint32_t ax = (addrA0 + bufo) ^ (uint32_t)(ks * 32);
            uint32_t bx = (addrB0 + bufo) ^ (uint32_t)(ks * 32);
            LDSM4(aHi, ax);
            LDSM4(aLo, ax + 8192);
            LDSM4(bh, bx);
            LDSM4(bl, bx + 16384);
#pragma unroll
            for (int nt2 = 0; nt2 < 16; nt2++) {
                uint32_t nh[4], nl[4];
                if (nt2 < 15) {
                    LDSM4(nh, bx + (nt2 + 1) * 1024);
                    LDSM4(nl, bx + (nt2 + 1) * 1024 + 16384);
                }
                float* d0 = acc + (2 * nt2) * 4;
                float* d1 = acc + (2 * nt2 + 1) * 4;
                MMA_BF16(d0, aHi, bh[0], bh[1]);
                MMA_BF16(d1, aHi, bh[2], bh[3]);
                MMA_BF16(d0, aLo, bh[0], bh[1]);
                MMA_BF16(d1, aLo, bh[2], bh[3]);
                MMA_BF16(d0, aHi, bl[0], bl[1]);
                MMA_BF16(d1, aHi, bl[2], bl[3]);
                if (nt2 < 15) {
#pragma unroll
                    for (int q = 0; q < 4; q++) { bh[q] = nh[q]; bl[q] = nl[q]; }
                }
            }
        }

        if (s < 7) CP_WAIT0();
        __syncthreads();

        if (s < 7) {
            float f[16] = {a0.x,a0.y,a0.z,a0.w, a1.x,a1.y,a1.z,a1.w,
                           a2.x,a2.y,a2.z,a2.w, a3.x,a3.y,a3.z,a3.w};
            uint32_t H[8], L[8];
#pragma unroll
            for (int e = 0; e < 16; e += 2) {
                x2p = fmaf(f[e], f[e], fmaf(f[e+1], f[e+1], x2p));
                float h0 = __bfloat162float(__float2bfloat16_rn(f[e]));
                float h1 = __bfloat162float(__float2bfloat16_rn(f[e+1]));
                H[e>>1] = pack_bf2(f[e], f[e+1]);
                L[e>>1] = pack_bf2(f[e] - h0, f[e+1] - h1);
            }
            *reinterpret_cast<uint4*>(dsm + nbufo + AHI + astoff0) = make_uint4(H[0],H[1],H[2],H[3]);
            *reinterpret_cast<uint4*>(dsm + nbufo + AHI + astoff1) = make_uint4(H[4],H[5],H[6],H[7]);
            *reinterpret_cast<uint4*>(dsm + nbufo + ALO + astoff0) = make_uint4(L[0],L[1],L[2],L[3]);
            *reinterpret_cast<uint4*>(dsm + nbufo + ALO + astoff1) = make_uint4(L[4],L[5],L[6],L[7]);
            __syncthreads();
        }
    }

    // ---- fused epilogue (all in registers / warp shuffles) ----
    // ||x_row||^2 : pair-combine -> lane lam holds total for row 16w + (lam>>1)
    float x2row = x2p + __shfl_xor_sync(0xffffffffu, x2p, 1);

    const int g  = l >> 2;
    const int t2 = (l & 3) * 2;

    float mx2a = 0.f, adba = 0.f, mx2b = 0.f, adbb = 0.f;
#pragma unroll
    for (int nt = 0; nt < 32; nt++) {
        float d0 = acc[nt*4+0], d1 = acc[nt*4+1];
        float d2 = acc[nt*4+2], d3 = acc[nt*4+3];
        float b0v = bsm[8*nt + t2], b1v = bsm[8*nt + t2 + 1];
        mx2a = fmaf(d0, d0, fmaf(d1, d1, mx2a));
        adba = fmaf(d0, b0v, fmaf(d1, b1v, adba));
        mx2b = fmaf(d2, d2, fmaf(d3, d3, mx2b));
        adbb = fmaf(d2, b0v, fmaf(d3, b1v, adbb));
    }
#pragma unroll
    for (int off = 1; off <= 2; off <<= 1) {
        mx2a += __shfl_xor_sync(0xffffffffu, mx2a, off);
        adba += __shfl_xor_sync(0xffffffffu, adba, off);
        mx2b += __shfl_xor_sync(0xffffffffu, mx2b, off);
        adbb += __shfl_xor_sync(0xffffffffu, adbb, off);
    }
    float x2a = __shfl_sync(0xffffffffu, x2row, 2 * g);
    float x2b = __shfl_sync(0xffffffffu, x2row, 2 * g + 16);

    float2 sa = hyp_scalars(x2a, mx2a, adba, b2sum);
    float2 sb = hyp_scalars(x2b, mx2b, adbb, b2sum);

    const int rowa = rowbase + 16 * w + g;
    const int rowb = rowa + 8;
    float* outa = out + (size_t)rowa * 256;
    float* outb = out + (size_t)rowb * 256;
    const bool oka = rowa < Nrows, okb = rowb < Nrows;
#pragma unroll
    for (int nt = 0; nt < 32; nt++) {
        int c0 = 8 * nt + t2;
        float b0v = bsm[c0], b1v = bsm[c0 + 1];
        if (oka) {
            float2 ov = make_float2(fmaf(sa.x, acc[nt*4+0], sa.y * b0v),
                                    fmaf(sa.x, acc[nt*4+1], sa.y * b1v));
            *reinterpret_cast<float2*>(outa + c0) = ov;
        }
        if (okb) {
            float2 ov = make_float2(fmaf(sb.x, acc[nt*4+2], sb.y * b0v),
                                    fmaf(sb.x, acc[nt*4+3], sb.y * b1v));
            *reinterpret_cast<float2*>(outb + c0) = ov;
        }
    }
}

extern "C" void kernel_launch(void* const* d_in, const int* in_sizes, int n_in,
                              void* d_out, int out_size) {
    const float* x = (const float*)d_in[0];
    const float* W = (const float*)d_in[1];
    const float* b = (const float*)d_in[2];
    float* out = (float*)d_out;
    int N = in_sizes[0] / 256;

    cudaFuncSetAttribute(hyplin_hmma_kernel,
                         cudaFuncAttributeMaxDynamicSharedMemorySize, DSMEM_BYTES);

    wconv_kernel<<<256, 256>>>(W);
    int grid = (N + 127) / 128;
    hyplin_hmma_kernel<<<grid, 256, DSMEM_BYTES>>>(x, b, out, N);
}

// round 7
// speedup vs baseline: 1.0003x; 1.0003x over previous
#include <cuda_runtime.h>
#include <cuda_bf16.h>
#include <cstdint>
#include <math.h>

#define HEPS   1e-7f
#define HMAXN  (1.0f - 1e-5f)

// ---------------- precomputed bf16 split of W ----------------
__device__ __align__(16) __nv_bfloat16 g_Whi[256 * 256];
__device__ __align__(16) __nv_bfloat16 g_Wlo[256 * 256];

__global__ void wconv_kernel(const float* __restrict__ W) {
    int i = blockIdx.x * blockDim.x + threadIdx.x;
    if (i < 256 * 256) {
        float w = W[i];
        __nv_bfloat16 h = __float2bfloat16_rn(w);
        g_Whi[i] = h;
        g_Wlo[i] = __float2bfloat16_rn(w - __bfloat162float(h));
    }
}

// ---------------- PTX helpers (all family-wide, compute_103-safe) ----------
#define LDSM4(R, addr)                                                        \
    asm volatile("ldmatrix.sync.aligned.m8n8.x4.shared.b16 {%0,%1,%2,%3}, [%4];" \
        : "=r"((R)[0]), "=r"((R)[1]), "=r"((R)[2]), "=r"((R)[3]) : "r"(addr))

#define MMA_BF16(D, A, B0, B1)                                                \
    asm volatile("mma.sync.aligned.m16n8k16.row.col.f32.bf16.bf16.f32 "       \
        "{%0,%1,%2,%3},{%4,%5,%6,%7},{%8,%9},{%0,%1,%2,%3};"                  \
        : "+f"((D)[0]), "+f"((D)[1]), "+f"((D)[2]), "+f"((D)[3])              \
        : "r"((A)[0]), "r"((A)[1]), "r"((A)[2]), "r"((A)[3]), "r"(B0), "r"(B1))

#define CP_ASYNC16(saddr, gaddr)                                              \
    asm volatile("cp.async.cg.shared.global [%0], [%1], 16;" :: "r"(saddr), "l"(gaddr))
#define CP_COMMIT()  asm volatile("cp.async.commit_group;" ::: "memory")
#define CP_WAIT0()   asm volatile("cp.async.wait_group 0;" ::: "memory")

__device__ __forceinline__ uint32_t smem_u32(const void* p) {
    return (uint32_t)__cvta_generic_to_shared(p);
}
__device__ __forceinline__ uint32_t pack_bf2(float a, float b) {
    __nv_bfloat162 t = __floats2bfloat162_rn(a, b);
    return reinterpret_cast<uint32_t&>(t);
}

// per-row hyperbolic scalars: out_j = Ca*mx_j + Cb*b_j  (validated in R2)
__device__ __forceinline__ float2 hyp_scalars(float x2, float mx2, float adb, float b2sum) {
    float xn  = fmaxf(sqrtf(x2),  HEPS);
    float mxn = fmaxf(sqrtf(mx2), HEPS);
    float xc  = fminf(xn, 1.0f - 1e-7f);
    float at  = 0.5f * (log1pf(xc) - log1pf(-xc));
    float tt  = tanhf(mxn / xn * at);
    float s1  = tt / mxn;
    float rn  = fmaxf(sqrtf(s1 * s1 * mx2), HEPS);
    float ps  = (rn > HMAXN) ? (HMAXN / rn) : 1.0f;
    float sres = s1 * ps;
    float res2 = sres * sres * mx2;

    float omr = 1.0f - res2;
    float vn  = fmaxf(sqrtf(omr * omr * b2sum), HEPS);
    float lam = 2.0f / fmaxf(omr, HEPS);
    float sc2 = tanhf(0.5f * lam * vn);
    float ksec = sc2 * omr / vn;

    float xy  = ksec * sres * adb;
    float y2  = ksec * ksec * b2sum;
    float den = fmaxf(1.0f + 2.0f * xy + res2 * y2, HEPS);
    float ca  = (1.0f + 2.0f * xy + y2) * sres / den;
    float cb  = omr * ksec / den;

    float o2  = ca * ca * mx2 + 2.0f * ca * cb * adb + cb * cb * b2sum;
    float on  = fmaxf(sqrtf(o2), HEPS);
    float pf  = (on > HMAXN) ? (HMAXN / on) : 1.0f;
    return make_float2(pf * ca, pf * cb);
}

// smem layout per buffer (64B row stride, 16B-unit XOR swizzle):
//   A_hi 8K | A_lo 8K | B_hi 16K | B_lo 16K   = 48K, double buffered = 96K
#define BUFS  49152
#define AHI   0
#define ALO   8192
#define BHI   16384
#define BLO   32768
#define DSMEM_BYTES (1024 + 2 * BUFS)

__global__ __launch_bounds__(256, 1)
void hyplin_hmma_kernel(const float* __restrict__ x,
                        const float* __restrict__ b,
                        float* __restrict__ out,
                        int Nrows)
{
    extern __shared__ char dsm_raw[];
    __shared__ float bsm[256];
    __shared__ float bpart[8];

    const int tid  = threadIdx.x;
    const int w    = tid >> 5;
    const int l    = tid & 31;
    const int rowbase = blockIdx.x * 128;

    // align dynamic smem to 1024B
    uint32_t raw = smem_u32(dsm_raw);
    uint32_t sbase = (raw + 1023u) & ~1023u;
    char* dsm = dsm_raw + (sbase - raw);

    // ---- bias + ||b||^2 ----
    {
        float bv = b[tid];
        bsm[tid] = bv;
        float sq = bv * bv;
#pragma unroll
        for (int off = 16; off; off >>= 1)
            sq += __shfl_xor_sync(0xffffffffu, sq, off);
        if (l == 0) bpart[w] = sq;
    }
    __syncthreads();
    float b2sum = 0.f;
#pragma unroll
    for (int i = 0; i < 8; i++) b2sum += bpart[i];

    // ---- loader mappings ----
    // A: thread t loads 16 fp32 of row (t>>1), cols (t&1)*16 .. +16
    const int arow = tid >> 1;
    int rg = rowbase + arow; if (rg >= Nrows) rg = Nrows - 1;
    const float* xrow = x + (size_t)rg * 256 + (tid & 1) * 16;
    const int asw = (arow >> 1) & 3;
    const int ac2 = (tid & 1) * 2;
    const uint32_t astoff0 = arow * 64 + ((ac2 + 0) ^ asw) * 16;
    const uint32_t astoff1 = arow * 64 + ((ac2 + 1) ^ asw) * 16;

    // B cp.async: thread handles uint4 idx = tid + j*256 (j=0..3) per matrix
    const int bc = tid & 3;                 // 16B unit (pre-swizzle)
    const int brow0 = tid >> 2;             // + 64*j

    float x2p = 0.f;
    float acc[128];
#pragma unroll
    for (int i = 0; i < 128; i++) acc[i] = 0.f;

    // ---- prologue: chunk 0 ----
    {
        float4 a0 = reinterpret_cast<const float4*>(xrow)[0];
        float4 a1 = reinterpret_cast<const float4*>(xrow)[1];
        float4 a2 = reinterpret_cast<const float4*>(xrow)[2];
        float4 a3 = reinterpret_cast<const float4*>(xrow)[3];
#pragma unroll
        for (int j = 0; j < 4; j++) {
            int row = brow0 + j * 64;
            uint32_t unit = (uint32_t)(bc ^ ((row >> 1) & 3));
            uint32_t so = sbase + BHI + row * 64 + unit * 16;
            const char* gh = (const char*)(g_Whi + (size_t)row * 256 + bc * 8);
            const char* gl = (const char*)(g_Wlo + (size_t)row * 256 + bc * 8);
            CP_ASYNC16(so, gh);
            CP_ASYNC16(so + 16384, gl);
        }
        CP_COMMIT();
        float f[16] = {a0.x,a0.y,a0.z,a0.w, a1.x,a1.y,a1.z,a1.w,
                       a2.x,a2.y,a2.z,a2.w, a3.x,a3.y,a3.z,a3.w};
        uint32_t H[8], L[8];
#pragma unroll
        for (int e = 0; e < 16; e += 2) {
            x2p = fmaf(f[e], f[e], fmaf(f[e+1], f[e+1], x2p));
            float h0 = __bfloat162float(__float2bfloat16_rn(f[e]));
            float h1 = __bfloat162float(__float2bfloat16_rn(f[e+1]));
            H[e>>1] = pack_bf2(f[e], f[e+1]);
            L[e>>1] = pack_bf2(f[e] - h0, f[e+1] - h1);
        }
        *reinterpret_cast<uint4*>(dsm + AHI + astoff0) = make_uint4(H[0],H[1],H[2],H[3]);
        *reinterpret_cast<uint4*>(dsm + AHI + astoff1) = make_uint4(H[4],H[5],H[6],H[7]);
        *reinterpret_cast<uint4*>(dsm + ALO + astoff0) = make_uint4(L[0],L[1],L[2],L[3]);
        *reinterpret_cast<uint4*>(dsm + ALO + astoff1) = make_uint4(L[4],L[5],L[6],L[7]);
        CP_WAIT0();
    }
    __syncthreads();

    // ---- ldmatrix lane address bases (buffer 0, ks=0) ----
    const int rowA = 16 * w + (l & 15);
    const uint32_t addrA0 = sbase + AHI + rowA * 64 +
                            (((l >> 4) ^ ((rowA >> 1) & 3)) * 16);
    const int nB   = (l & 7) + ((l >> 4) << 3);
    const int klo  = (l >> 3) & 1;
    const uint32_t addrB0 = sbase + BHI + nB * 64 +
                            ((klo ^ ((nB >> 1) & 3)) * 16);

    // ---- main pipelined loop over 8 K-chunks ----
    for (int s = 0; s < 8; s++) {
        const uint32_t bufo  = (uint32_t)(s & 1) * BUFS;
        const uint32_t nbufo = (uint32_t)((s + 1) & 1) * BUFS;

        // prefetch next chunk: A into regs, B via cp.async
        float4 a0, a1, a2, a3;
        if (s < 7) {
            const float* src = xrow + (s + 1) * 32;
            a0 = reinterpret_cast<const float4*>(src)[0];
            a1 = reinterpret_cast<const float4*>(src)[1];
            a2 = reinterpret_cast<const float4*>(src)[2];
            a3 = reinterpret_cast<const float4*>(src)[3];
#pragma unroll
            for (int j = 0; j < 4; j++) {
                int row = brow0 + j * 64;
                uint32_t unit = (uint32_t)(bc ^ ((row >> 1) & 3));
                uint32_t so = sbase + nbufo + BHI + row * 64 + unit * 16;
                const char* gh = (const char*)(g_Whi + (size_t)row * 256 + (s+1) * 32 + bc * 8);
                const char* gl = (const char*)(g_Wlo + (size_t)row * 256 + (s+1) * 32 + bc * 8);
                CP_ASYNC16(so, gh);
                CP_ASYNC16(so + 16384, gl);
            }
            CP_COMMIT();
        }

        // ---- MMA over this chunk (KT=32 -> 2 ksteps of k16) ----
        uint32_t aHi[4], aLo[4], bh[4], bl[4];
#pragma unroll
        for (int ks = 0; ks < 2; ks++) {
            uint32_t ax = (addrA0 + bufo) ^ (uint32_t)(ks * 32);
            uint32_t bx = (addrB0 + bufo) ^ (uint32_t)(ks * 32);
            LDSM4(aHi, ax);
            LDSM4(aLo, ax + 8192);
            LDSM4(bh, bx);
            LDSM4(bl, bx + 16384);
#pragma unroll
            for (int nt2 = 0; nt2 < 16; nt2++) {
                uint32_t nh[4], nl[4];
                if (nt2 < 15) {
                    LDSM4(nh, bx + (nt2 + 1) * 1024);
                    LDSM4(nl, bx + (nt2 + 1) * 1024 + 16384);
                }
                float* d0 = acc + (2 * nt2) * 4;
                float* d1 = acc + (2 * nt2 + 1) * 4;
                MMA_BF16(d0, aHi, bh[0], bh[1]);
                MMA_BF16(d1, aHi, bh[2], bh[3]);
                MMA_BF16(d0, aLo, bh[0], bh[1]);
                MMA_BF16(d1, aLo, bh[2], bh[3]);
                MMA_BF16(d0, aHi, bl[0], bl[1]);
                MMA_BF16(d1, aHi, bl[2], bl[3]);
                if (nt2 < 15) {
#pragma unroll
                    for (int q = 0; q < 4; q++) { bh[q] = nh[q]; bl[q] = nl[q]; }
                }
            }
        }

        if (s < 7) CP_WAIT0();
        __syncthreads();

        if (s < 7) {
            float f[16] = {a0.x,a0.y,a0.z,a0.w, a1.x,a1.y,a1.z,a1.w,
                           a2.x,a2.y,a2.z,a2.w, a3.x,a3.y,a3.z,a3.w};
            uint32_t H[8], L[8];
#pragma unroll
            for (int e = 0; e < 16; e += 2) {
                x2p = fmaf(f[e], f[e], fmaf(f[e+1], f[e+1], x2p));
                float h0 = __bfloat162float(__float2bfloat16_rn(f[e]));
                float h1 = __bfloat162float(__float2bfloat16_rn(f[e+1]));
                H[e>>1] = pack_bf2(f[e], f[e+1]);
                L[e>>1] = pack_bf2(f[e] - h0, f[e+1] - h1);
            }
            *reinterpret_cast<uint4*>(dsm + nbufo + AHI + astoff0) = make_uint4(H[0],H[1],H[2],H[3]);
            *reinterpret_cast<uint4*>(dsm + nbufo + AHI + astoff1) = make_uint4(H[4],H[5],H[6],H[7]);
            *reinterpret_cast<uint4*>(dsm + nbufo + ALO + astoff0) = make_uint4(L[0],L[1],L[2],L[3]);
            *reinterpret_cast<uint4*>(dsm + nbufo + ALO + astoff1) = make_uint4(L[4],L[5],L[6],L[7]);
            __syncthreads();
        }
    }

    // ---- fused epilogue (all in registers / warp shuffles) ----
    // ||x_row||^2 : pair-combine -> lane lam holds total for row 16w + (lam>>1)
    float x2row = x2p + __shfl_xor_sync(0xffffffffu, x2p, 1);

    const int g  = l >> 2;
    const int t2 = (l & 3) * 2;

    float mx2a = 0.f, adba = 0.f, mx2b = 0.f, adbb = 0.f;
#pragma unroll
    for (int nt = 0; nt < 32; nt++) {
        float d0 = acc[nt*4+0], d1 = acc[nt*4+1];
        float d2 = acc[nt*4+2], d3 = acc[nt*4+3];
        float b0v = bsm[8*nt + t2], b1v = bsm[8*nt + t2 + 1];
        mx2a = fmaf(d0, d0, fmaf(d1, d1, mx2a));
        adba = fmaf(d0, b0v, fmaf(d1, b1v, adba));
        mx2b = fmaf(d2, d2, fmaf(d3, d3, mx2b));
        adbb = fmaf(d2, b0v, fmaf(d3, b1v, adbb));
    }
#pragma unroll
    for (int off = 1; off <= 2; off <<= 1) {
        mx2a += __shfl_xor_sync(0xffffffffu, mx2a, off);
        adba += __shfl_xor_sync(0xffffffffu, adba, off);
        mx2b += __shfl_xor_sync(0xffffffffu, mx2b, off);
        adbb += __shfl_xor_sync(0xffffffffu, adbb, off);
    }
    float x2a = __shfl_sync(0xffffffffu, x2row, 2 * g);
    float x2b = __shfl_sync(0xffffffffu, x2row, 2 * g + 16);

    float2 sa = hyp_scalars(x2a, mx2a, adba, b2sum);
    float2 sb = hyp_scalars(x2b, mx2b, adbb, b2sum);

    const int rowa = rowbase + 16 * w + g;
    const int rowb = rowa + 8;
    float* outa = out + (size_t)rowa * 256;
    float* outb = out + (size_t)rowb * 256;
    const bool oka = rowa < Nrows, okb = rowb < Nrows;
#pragma unroll
    for (int nt = 0; nt < 32; nt++) {
        int c0 = 8 * nt + t2;
        float b0v = bsm[c0], b1v = bsm[c0 + 1];
        if (oka) {
            float2 ov = make_float2(fmaf(sa.x, acc[nt*4+0], sa.y * b0v),
                                    fmaf(sa.x, acc[nt*4+1], sa.y * b1v));
            *reinterpret_cast<float2*>(outa + c0) = ov;
        }
        if (okb) {
            float2 ov = make_float2(fmaf(sb.x, acc[nt*4+2], sb.y * b0v),
                                    fmaf(sb.x, acc[nt*4+3], sb.y * b1v));
            *reinterpret_cast<float2*>(outb + c0) = ov;
        }
    }
}

extern "C" void kernel_launch(void* const* d_in, const int* in_sizes, int n_in,
                              void* d_out, int out_size) {
    const float* x = (const float*)d_in[0];
    const float* W = (const float*)d_in[1];
    const float* b = (const float*)d_in[2];
    float* out = (float*)d_out;
    int N = in_sizes[0] / 256;

    cudaFuncSetAttribute(hyplin_hmma_kernel,
                         cudaFuncAttributeMaxDynamicSharedMemorySize, DSMEM_BYTES);

    wconv_kernel<<<256, 256>>>(W);
    int grid = (N + 127) / 128;
    hyplin_hmma_kernel<<<grid, 256, DSMEM_BYTES>>>(x, b, out, N);
}

// round 8
// speedup vs baseline: 1.0027x; 1.0024x over previous
#include <cuda_runtime.h>
#include <cuda_bf16.h>
#include <cstdint>
#include <math.h>

#define HEPS   1e-7f
#define HMAXN  (1.0f - 1e-5f)

// ---------------- precomputed bf16 split of W ----------------
__device__ __align__(16) __nv_bfloat16 g_Whi[256 * 256];
__device__ __align__(16) __nv_bfloat16 g_Wlo[256 * 256];

__global__ void wconv_kernel(const float* __restrict__ W) {
    int i = blockIdx.x * blockDim.x + threadIdx.x;
    if (i < 256 * 256) {
        float w = W[i];
        __nv_bfloat16 h = __float2bfloat16_rn(w);
        g_Whi[i] = h;
        g_Wlo[i] = __float2bfloat16_rn(w - __bfloat162float(h));
    }
}

// ---------------- PTX helpers (all family-wide, compute_103-safe) ----------
#define LDSM4(R, addr)                                                        \
    asm volatile("ldmatrix.sync.aligned.m8n8.x4.shared.b16 {%0,%1,%2,%3}, [%4];" \
        : "=r"((R)[0]), "=r"((R)[1]), "=r"((R)[2]), "=r"((R)[3]) : "r"(addr))

#define MMA_BF16(D, A, B0, B1)                                                \
    asm volatile("mma.sync.aligned.m16n8k16.row.col.f32.bf16.bf16.f32 "       \
        "{%0,%1,%2,%3},{%4,%5,%6,%7},{%8,%9},{%0,%1,%2,%3};"                  \
        : "+f"((D)[0]), "+f"((D)[1]), "+f"((D)[2]), "+f"((D)[3])              \
        : "r"((A)[0]), "r"((A)[1]), "r"((A)[2]), "r"((A)[3]), "r"(B0), "r"(B1))

#define CP_ASYNC16(saddr, gaddr)                                              \
    asm volatile("cp.async.cg.shared.global [%0], [%1], 16;" :: "r"(saddr), "l"(gaddr))
#define CP_COMMIT()  asm volatile("cp.async.commit_group;" ::: "memory")
#define CP_WAIT0()   asm volatile("cp.async.wait_group 0;" ::: "memory")

__device__ __forceinline__ uint32_t smem_u32(const void* p) {
    return (uint32_t)__cvta_generic_to_shared(p);
}
__device__ __forceinline__ uint32_t pack_bf2(float a, float b) {
    __nv_bfloat162 t = __floats2bfloat162_rn(a, b);
    return reinterpret_cast<uint32_t&>(t);
}

// per-row hyperbolic scalars: out_j = Ca*mx_j + Cb*b_j  (validated in R2)
__device__ __forceinline__ float2 hyp_scalars(float x2, float mx2, float adb, float b2sum) {
    float xn  = fmaxf(sqrtf(x2),  HEPS);
    float mxn = fmaxf(sqrtf(mx2), HEPS);
    float xc  = fminf(xn, 1.0f - 1e-7f);
    float at  = 0.5f * (log1pf(xc) - log1pf(-xc));
    float tt  = tanhf(mxn / xn * at);
    float s1  = tt / mxn;
    float rn  = fmaxf(sqrtf(s1 * s1 * mx2), HEPS);
    float ps  = (rn > HMAXN) ? (HMAXN / rn) : 1.0f;
    float sres = s1 * ps;
    float res2 = sres * sres * mx2;

    float omr = 1.0f - res2;
    float vn  = fmaxf(sqrtf(omr * omr * b2sum), HEPS);
    float lam = 2.0f / fmaxf(omr, HEPS);
    float sc2 = tanhf(0.5f * lam * vn);
    float ksec = sc2 * omr / vn;

    float xy  = ksec * sres * adb;
    float y2  = ksec * ksec * b2sum;
    float den = fmaxf(1.0f + 2.0f * xy + res2 * y2, HEPS);
    float ca  = (1.0f + 2.0f * xy + y2) * sres / den;
    float cb  = omr * ksec / den;

    float o2  = ca * ca * mx2 + 2.0f * ca * cb * adb + cb * cb * b2sum;
    float on  = fmaxf(sqrtf(o2), HEPS);
    float pf  = (on > HMAXN) ? (HMAXN / on) : 1.0f;
    return make_float2(pf * ca, pf * cb);
}

// smem layout per buffer (64B row stride, 16B-unit XOR swizzle):
//   A_hi 8K | A_lo 8K | B_hi 16K | B_lo 16K   = 48K, double buffered = 96K
#define BUFS  49152
#define AHI   0
#define ALO   8192
#define BHI   16384
#define BLO   32768
#define DSMEM_BYTES (1024 + 2 * BUFS)

__global__ __launch_bounds__(256, 1)
void hyplin_hmma_kernel(const float* __restrict__ x,
                        const float* __restrict__ b,
                        float* __restrict__ out,
                        int Nrows)
{
    extern __shared__ char dsm_raw[];
    __shared__ float bsm[256];
    __shared__ float bpart[8];

    const int tid  = threadIdx.x;
    const int w    = tid >> 5;
    const int l    = tid & 31;
    const int rowbase = blockIdx.x * 128;

    // align dynamic smem to 1024B
    uint32_t raw = smem_u32(dsm_raw);
    uint32_t sbase = (raw + 1023u) & ~1023u;
    char* dsm = dsm_raw + (sbase - raw);

    // ---- bias + ||b||^2 ----
    {
        float bv = b[tid];
        bsm[tid] = bv;
        float sq = bv * bv;
#pragma unroll
        for (int off = 16; off; off >>= 1)
            sq += __shfl_xor_sync(0xffffffffu, sq, off);
        if (l == 0) bpart[w] = sq;
    }
    __syncthreads();
    float b2sum = 0.f;
#pragma unroll
    for (int i = 0; i < 8; i++) b2sum += bpart[i];

    // ---- loader mappings ----
    // A: thread t loads 16 fp32 of row (t>>1), cols (t&1)*16 .. +16
    const int arow = tid >> 1;
    int rg = rowbase + arow; if (rg >= Nrows) rg = Nrows - 1;
    const float* xrow = x + (size_t)rg * 256 + (tid & 1) * 16;
    const int asw = (arow >> 1) & 3;
    const int ac2 = (tid & 1) * 2;
    const uint32_t astoff0 = arow * 64 + ((ac2 + 0) ^ asw) * 16;
    const uint32_t astoff1 = arow * 64 + ((ac2 + 1) ^ asw) * 16;

    // B cp.async: thread handles uint4 idx = tid + j*256 (j=0..3) per matrix
    const int bc = tid & 3;                 // 16B unit (pre-swizzle)
    const int brow0 = tid >> 2;             // + 64*j

    float x2p = 0.f;
    float acc[128];
#pragma unroll
    for (int i = 0; i < 128; i++) acc[i] = 0.f;

    // ---- prologue: chunk 0 ----
    {
        float4 a0 = reinterpret_cast<const float4*>(xrow)[0];
        float4 a1 = reinterpret_cast<const float4*>(xrow)[1];
        float4 a2 = reinterpret_cast<const float4*>(xrow)[2];
        float4 a3 = reinterpret_cast<const float4*>(xrow)[3];
#pragma unroll
        for (int j = 0; j < 4; j++) {
            int row = brow0 + j * 64;
            uint32_t unit = (uint32_t)(bc ^ ((row >> 1) & 3));
            uint32_t so = sbase + BHI + row * 64 + unit * 16;
            const char* gh = (const char*)(g_Whi + (size_t)row * 256 + bc * 8);
            const char* gl = (const char*)(g_Wlo + (size_t)row * 256 + bc * 8);
            CP_ASYNC16(so, gh);
            CP_ASYNC16(so + 16384, gl);
        }
        CP_COMMIT();
        float f[16] = {a0.x,a0.y,a0.z,a0.w, a1.x,a1.y,a1.z,a1.w,
                       a2.x,a2.y,a2.z,a2.w, a3.x,a3.y,a3.z,a3.w};
        uint32_t H[8], L[8];
#pragma unroll
        for (int e = 0; e < 16; e += 2) {
            x2p = fmaf(f[e], f[e], fmaf(f[e+1], f[e+1], x2p));
            float h0 = __bfloat162float(__float2bfloat16_rn(f[e]));
            float h1 = __bfloat162float(__float2bfloat16_rn(f[e+1]));
            H[e>>1] = pack_bf2(f[e], f[e+1]);
            L[e>>1] = pack_bf2(f[e] - h0, f[e+1] - h1);
        }
        *reinterpret_cast<uint4*>(dsm + AHI + astoff0) = make_uint4(H[0],H[1],H[2],H[3]);
        *reinterpret_cast<uint4*>(dsm + AHI + astoff1) = make_uint4(H[4],H[5],H[6],H[7]);
        *reinterpret_cast<uint4*>(dsm + ALO + astoff0) = make_uint4(L[0],L[1],L[2],L[3]);
        *reinterpret_cast<uint4*>(dsm + ALO + astoff1) = make_uint4(L[4],L[5],L[6],L[7]);
        CP_WAIT0();
    }
    __syncthreads();

    // ---- ldmatrix lane address bases (buffer 0, ks=0) ----
    const int rowA = 16 * w + (l & 15);
    const uint32_t addrA0 = sbase + AHI + rowA * 64 +
                            (((l >> 4) ^ ((rowA >> 1) & 3)) * 16);
    const int nB   = (l & 7) + ((l >> 4) << 3);
    const int klo  = (l >> 3) & 1;
    const uint32_t addrB0 = sbase + BHI + nB * 64 +
                            ((klo ^ ((nB >> 1) & 3)) * 16);

    // ---- main pipelined loop over 8 K-chunks ----
    for (int s = 0; s < 8; s++) {
        const uint32_t bufo  = (uint32_t)(s & 1) * BUFS;
        const uint32_t nbufo = (uint32_t)((s + 1) & 1) * BUFS;

        // prefetch next chunk: A into regs, B via cp.async
        float4 a0, a1, a2, a3;
        if (s < 7) {
            const float* src = xrow + (s + 1) * 32;
            a0 = reinterpret_cast<const float4*>(src)[0];
            a1 = reinterpret_cast<const float4*>(src)[1];
            a2 = reinterpret_cast<const float4*>(src)[2];
            a3 = reinterpret_cast<const float4*>(src)[3];
#pragma unroll
            for (int j = 0; j < 4; j++) {
                int row = brow0 + j * 64;
                uint32_t unit = (uint32_t)(bc ^ ((row >> 1) & 3));
                uint32_t so = sbase + nbufo + BHI + row * 64 + unit * 16;
                const char* gh = (const char*)(g_Whi + (size_t)row * 256 + (s+1) * 32 + bc * 8);
                const char* gl = (const char*)(g_Wlo + (size_t)row * 256 + (s+1) * 32 + bc * 8);
                CP_ASYNC16(so, gh);
                CP_ASYNC16(so + 16384, gl);
            }
            CP_COMMIT();
        }

        // ---- MMA over this chunk (KT=32 -> 2 ksteps of k16) ----
        uint32_t aHi[4], aLo[4], bh[4], bl[4];
#pragma unroll
        for (int ks = 0; ks < 2; ks++) {
            uint32_t ax = (addrA0 + bufo) ^ (uint32_t)(ks * 32);
            uint32_t bx = (addrB0 + bufo) ^ (uint32_t)(ks * 32);
            LDSM4(aHi, ax);
            LDSM4(aLo, ax + 8192);
            LDSM4(bh, bx);
            LDSM4(bl, bx + 16384);
#pragma unroll
            for (int nt2 = 0; nt2 < 16; nt2++) {
                uint32_t nh[4], nl[4];
                if (nt2 < 15) {
                    LDSM4(nh, bx + (nt2 + 1) * 1024);
                    LDSM4(nl, bx + (nt2 + 1) * 1024 + 16384);
                }
                float* d0 = acc + (2 * nt2) * 4;
                float* d1 = acc + (2 * nt2 + 1) * 4;
                MMA_BF16(d0, aHi, bh[0], bh[1]);
                MMA_BF16(d1, aHi, bh[2], bh[3]);
                MMA_BF16(d0, aLo, bh[0], bh[1]);
                MMA_BF16(d1, aLo, bh[2], bh[3]);
                MMA_BF16(d0, aHi, bl[0], bl[1]);
                MMA_BF16(d1, aHi, bl[2], bl[3]);
                if (nt2 < 15) {
#pragma unroll
                    for (int q = 0; q < 4; q++) { bh[q] = nh[q]; bl[q] = nl[q]; }
                }
            }
        }

        if (s < 7) CP_WAIT0();
        __syncthreads();

        if (s < 7) {
            float f[16] = {a0.x,a0.y,a0.z,a0.w, a1.x,a1.y,a1.z,a1.w,
                           a2.x,a2.y,a2.z,a2.w, a3.x,a3.y,a3.z,a3.w};
            uint32_t H[8], L[8];
#pragma unroll
            for (int e = 0; e < 16; e += 2) {
                x2p = fmaf(f[e], f[e], fmaf(f[e+1], f[e+1], x2p));
                float h0 = __bfloat162float(__float2bfloat16_rn(f[e]));
                float h1 = __bfloat162float(__float2bfloat16_rn(f[e+1]));
                H[e>>1] = pack_bf2(f[e], f[e+1]);
                L[e>>1] = pack_bf2(f[e] - h0, f[e+1] - h1);
            }
            *reinterpret_cast<uint4*>(dsm + nbufo + AHI + astoff0) = make_uint4(H[0],H[1],H[2],H[3]);
            *reinterpret_cast<uint4*>(dsm + nbufo + AHI + astoff1) = make_uint4(H[4],H[5],H[6],H[7]);
            *reinterpret_cast<uint4*>(dsm + nbufo + ALO + astoff0) = make_uint4(L[0],L[1],L[2],L[3]);
            *reinterpret_cast<uint4*>(dsm + nbufo + ALO + astoff1) = make_uint4(L[4],L[5],L[6],L[7]);
            __syncthreads();
        }
    }

    // ---- fused epilogue (all in registers / warp shuffles) ----
    // ||x_row||^2 : pair-combine -> lane lam holds total for row 16w + (lam>>1)
    float x2row = x2p + __shfl_xor_sync(0xffffffffu, x2p, 1);

    const int g  = l >> 2;
    const int t2 = (l & 3) * 2;

    float mx2a = 0.f, adba = 0.f, mx2b = 0.f, adbb = 0.f;
#pragma unroll
    for (int nt = 0; nt < 32; nt++) {
        float d0 = acc[nt*4+0], d1 = acc[nt*4+1];
        float d2 = acc[nt*4+2], d3 = acc[nt*4+3];
        float b0v = bsm[8*nt + t2], b1v = bsm[8*nt + t2 + 1];
        mx2a = fmaf(d0, d0, fmaf(d1, d1, mx2a));
        adba = fmaf(d0, b0v, fmaf(d1, b1v, adba));
        mx2b = fmaf(d2, d2, fmaf(d3, d3, mx2b));
        adbb = fmaf(d2, b0v, fmaf(d3, b1v, adbb));
    }
#pragma unroll
    for (int off = 1; off <= 2; off <<= 1) {
        mx2a += __shfl_xor_sync(0xffffffffu, mx2a, off);
        adba += __shfl_xor_sync(0xffffffffu, adba, off);
        mx2b += __shfl_xor_sync(0xffffffffu, mx2b, off);
        adbb += __shfl_xor_sync(0xffffffffu, adbb, off);
    }
    float x2a = __shfl_sync(0xffffffffu, x2row, 2 * g);
    float x2b = __shfl_sync(0xffffffffu, x2row, 2 * g + 16);

    float2 sa = hyp_scalars(x2a, mx2a, adba, b2sum);
    float2 sb = hyp_scalars(x2b, mx2b, adbb, b2sum);

    const int rowa = rowbase + 16 * w + g;
    const int rowb = rowa + 8;
    float* outa = out + (size_t)rowa * 256;
    float* outb = out + (size_t)rowb * 256;
    const bool oka = rowa < Nrows, okb = rowb < Nrows;
#pragma unroll
    for (int nt = 0; nt < 32; nt++) {
        int c0 = 8 * nt + t2;
        float b0v = bsm[c0], b1v = bsm[c0 + 1];
        if (oka) {
            float2 ov = make_float2(fmaf(sa.x, acc[nt*4+0], sa.y * b0v),
                                    fmaf(sa.x, acc[nt*4+1], sa.y * b1v));
            *reinterpret_cast<float2*>(outa + c0) = ov;
        }
        if (okb) {
            float2 ov = make_float2(fmaf(sb.x, acc[nt*4+2], sb.y * b0v),
                                    fmaf(sb.x, acc[nt*4+3], sb.y * b1v));
            *reinterpret_cast<float2*>(outb + c0) = ov;
        }
    }
}

extern "C" void kernel_launch(void* const* d_in, const int* in_sizes, int n_in,
                              void* d_out, int out_size) {
    const float* x = (const float*)d_in[0];
    const float* W = (const float*)d_in[1];
    const float* b = (const float*)d_in[2];
    float* out = (float*)d_out;
    int N = in_sizes[0] / 256;

    cudaFuncSetAttribute(hyplin_hmma_kernel,
                         cudaFuncAttributeMaxDynamicSharedMemorySize, DSMEM_BYTES);

    wconv_kernel<<<256, 256>>>(W);
    int grid = (N + 127) / 128;
    hyplin_hmma_kernel<<<grid, 256, DSMEM_BYTES>>>(x, b, out, N);
}